// round 2
// baseline (speedup 1.0000x reference)
#include <cuda_runtime.h>
#include <math.h>

#define T_TOK 2048
#define HD    2048
#define ID    768
#define NE    32
#define TOPK  4
#define NPAIR (T_TOK*TOPK)

// ---------------- scratch (__device__ globals; no dynamic alloc) ----------------
__device__ int   g_cnt[NE];
__device__ int   g_off[NE];
__device__ int   g_cur[NE];
__device__ int   g_pair_tok[NPAIR];
__device__ float g_pair_w[NPAIR];
__device__ int   g_tk_id[NPAIR];
__device__ float g_tk_w[NPAIR];
// +64 rows of padding so partially-filled m-tiles can be read harmlessly
__device__ float g_act[(size_t)(NPAIR + 64) * ID];

// ---------------- kernel 0: zero per-expert counters ----------------
__global__ void zero_cnt_kernel() {
    if (threadIdx.x < NE) g_cnt[threadIdx.x] = 0;
}

// ---------------- kernel 1: router (logits -> top4 -> softmax weights) ----------------
__global__ void router_kernel(const float* __restrict__ x, const float* __restrict__ gw) {
    __shared__ float xs[HD];
    __shared__ float lg[NE];
    int t = blockIdx.x;
    const float4* xv  = (const float4*)(x + (size_t)t * HD);
    float4*       xsv = (float4*)xs;
    for (int i = threadIdx.x; i < HD/4; i += blockDim.x) xsv[i] = xv[i];
    __syncthreads();
    int warp = threadIdx.x >> 5, lane = threadIdx.x & 31;
    for (int e = warp; e < NE; e += 8) {
        const float4* w = (const float4*)(gw + (size_t)e * HD);
        float s = 0.f;
        #pragma unroll 4
        for (int h = lane; h < HD/4; h += 32) {
            float4 wv = w[h];
            float4 xr = xsv[h];
            s += wv.x*xr.x + wv.y*xr.y + wv.z*xr.z + wv.w*xr.w;
        }
        #pragma unroll
        for (int o = 16; o; o >>= 1) s += __shfl_xor_sync(0xffffffffu, s, o);
        if (lane == 0) lg[e] = s;
    }
    __syncthreads();
    if (threadIdx.x == 0) {
        int sel[TOPK]; float sv[TOPK];
        unsigned used = 0u;
        #pragma unroll
        for (int k = 0; k < TOPK; k++) {
            float best = -1e30f; int bi = 0;
            for (int e2 = 0; e2 < NE; e2++)
                if (!((used >> e2) & 1u) && lg[e2] > best) { best = lg[e2]; bi = e2; }
            used |= 1u << bi; sel[k] = bi; sv[k] = best;
        }
        // softmax over the selected 4 == renormalized full-softmax top-4
        float mx = sv[0], den = 0.f, ww[TOPK];
        #pragma unroll
        for (int k = 0; k < TOPK; k++) { ww[k] = expf(sv[k] - mx); den += ww[k]; }
        #pragma unroll
        for (int k = 0; k < TOPK; k++) {
            g_tk_id[t*TOPK + k] = sel[k];
            g_tk_w [t*TOPK + k] = ww[k] / den;
            atomicAdd(&g_cnt[sel[k]], 1);
        }
    }
}

// ---------------- kernel 2: exclusive scan of counts ----------------
__global__ void scan_kernel() {
    if (threadIdx.x == 0) {
        int acc = 0;
        for (int e = 0; e < NE; e++) { g_off[e] = acc; g_cur[e] = acc; acc += g_cnt[e]; }
    }
}

// ---------------- kernel 3: fill expert-grouped pair lists ----------------
__global__ void fill_kernel() {
    int p = blockIdx.x * blockDim.x + threadIdx.x;
    if (p >= NPAIR) return;
    int e   = g_tk_id[p];
    int pos = atomicAdd(&g_cur[e], 1);
    g_pair_tok[pos] = p >> 2;
    g_pair_w  [pos] = g_tk_w[p];
}

// ---------------- kernel 4: stage A  (X @ Wg, X @ Wu -> silu(g)*u*w) ----------------
// block: 256 thr (16x16), tile 64(tok) x 64(I), KB=16
__global__ __launch_bounds__(256, 2)
void stageA_kernel(const float* __restrict__ x,
                   const float* __restrict__ Wg, const float* __restrict__ Wu) {
    int e = blockIdx.z;
    int cnt = g_cnt[e];
    int m0 = blockIdx.y * 64;
    if (m0 >= cnt) return;
    int off = g_off[e];
    int n0  = blockIdx.x * 64;

    __shared__ float Xs[16][68];
    __shared__ float Bgs[16][64];
    __shared__ float Bus[16][64];
    __shared__ int   toks[64];
    __shared__ float wts[64];

    int tid = threadIdx.x;
    if (tid < 64) {
        int r = m0 + tid;
        toks[tid] = (r < cnt) ? g_pair_tok[off + r] : 0;
        wts[tid]  = (r < cnt) ? g_pair_w [off + r] : 0.f;
    }
    __syncthreads();

    int lr = tid >> 2;            // 0..63 : X row within tile
    int lk = (tid & 3) * 4;       // 0,4,8,12 : k quad
    const float* xrow = x + (size_t)toks[lr] * HD + lk;

    int br = tid >> 4;            // 0..15 : B k-row
    int bc = (tid & 15) * 4;      // 0..60 : B col quad
    const float* gptr = Wg + (size_t)e * HD * ID + (size_t)br * ID + n0 + bc;
    const float* uptr = Wu + (size_t)e * HD * ID + (size_t)br * ID + n0 + bc;

    int tx = tid & 15, ty = tid >> 4;
    float ag[4][4] = {}, au[4][4] = {};

    for (int k0 = 0; k0 < HD; k0 += 16) {
        float4 xv = *(const float4*)(xrow + k0);
        float4 gv = *(const float4*)(gptr + (size_t)k0 * ID);
        float4 uv = *(const float4*)(uptr + (size_t)k0 * ID);
        __syncthreads();
        Xs[lk+0][lr] = xv.x; Xs[lk+1][lr] = xv.y; Xs[lk+2][lr] = xv.z; Xs[lk+3][lr] = xv.w;
        *(float4*)&Bgs[br][bc] = gv;
        *(float4*)&Bus[br][bc] = uv;
        __syncthreads();
        #pragma unroll
        for (int kk = 0; kk < 16; kk++) {
            float4 xr = *(const float4*)&Xs[kk][ty*4];
            float4 bg = *(const float4*)&Bgs[kk][tx*4];
            float4 bu = *(const float4*)&Bus[kk][tx*4];
            float xa[4] = {xr.x, xr.y, xr.z, xr.w};
            float ga[4] = {bg.x, bg.y, bg.z, bg.w};
            float ua[4] = {bu.x, bu.y, bu.z, bu.w};
            #pragma unroll
            for (int i2 = 0; i2 < 4; i2++)
                #pragma unroll
                for (int j = 0; j < 4; j++) {
                    ag[i2][j] += xa[i2] * ga[j];
                    au[i2][j] += xa[i2] * ua[j];
                }
        }
    }

    #pragma unroll
    for (int i2 = 0; i2 < 4; i2++) {
        int r = m0 + ty*4 + i2;
        if (r >= cnt) continue;
        float wr = wts[ty*4 + i2];
        float4 o;
        float v[4];
        #pragma unroll
        for (int j = 0; j < 4; j++) {
            float g = ag[i2][j];
            float s = g / (1.f + __expf(-g));      // silu
            v[j] = s * au[i2][j] * wr;
        }
        o.x = v[0]; o.y = v[1]; o.z = v[2]; o.w = v[3];
        *(float4*)(g_act + (size_t)(off + r) * ID + n0 + tx*4) = o;
    }
}

// ---------------- kernel 5: stage B  (A @ Wd -> atomic scatter-add into out) ----------------
__global__ __launch_bounds__(256, 2)
void stageB_kernel(const float* __restrict__ Wd, float* __restrict__ out) {
    int e = blockIdx.z;
    int cnt = g_cnt[e];
    int m0 = blockIdx.y * 64;
    if (m0 >= cnt) return;
    int off = g_off[e];
    int n0  = blockIdx.x * 64;

    __shared__ float As[16][68];
    __shared__ float Bs[16][64];
    __shared__ int   toks[64];

    int tid = threadIdx.x;
    if (tid < 64) {
        int r = m0 + tid;
        toks[tid] = (r < cnt) ? g_pair_tok[off + r] : 0;
    }
    __syncthreads();

    int lr = tid >> 2;
    int lk = (tid & 3) * 4;
    const float* arow = g_act + (size_t)(off + m0 + lr) * ID + lk;

    int br = tid >> 4;
    int bc = (tid & 15) * 4;
    const float* bptr = Wd + (size_t)e * ID * HD + (size_t)br * HD + n0 + bc;

    int tx = tid & 15, ty = tid >> 4;
    float acc[4][4] = {};

    for (int k0 = 0; k0 < ID; k0 += 16) {
        float4 av = *(const float4*)(arow + k0);
        float4 bv = *(const float4*)(bptr + (size_t)k0 * HD);
        __syncthreads();
        As[lk+0][lr] = av.x; As[lk+1][lr] = av.y; As[lk+2][lr] = av.z; As[lk+3][lr] = av.w;
        *(float4*)&Bs[br][bc] = bv;
        __syncthreads();
        #pragma unroll
        for (int kk = 0; kk < 16; kk++) {
            float4 ar = *(const float4*)&As[kk][ty*4];
            float4 bb = *(const float4*)&Bs[kk][tx*4];
            float aa[4] = {ar.x, ar.y, ar.z, ar.w};
            float ba[4] = {bb.x, bb.y, bb.z, bb.w};
            #pragma unroll
            for (int i2 = 0; i2 < 4; i2++)
                #pragma unroll
                for (int j = 0; j < 4; j++)
                    acc[i2][j] += aa[i2] * ba[j];
        }
    }

    #pragma unroll
    for (int i2 = 0; i2 < 4; i2++) {
        int r = m0 + ty*4 + i2;
        if (r >= cnt) continue;
        int tok = toks[ty*4 + i2];
        float* po = out + (size_t)tok * HD + n0 + tx*4;
        #pragma unroll
        for (int j = 0; j < 4; j++) atomicAdd(po + j, acc[i2][j]);
    }
}

// ---------------- launch ----------------
extern "C" void kernel_launch(void* const* d_in, const int* in_sizes, int n_in,
                              void* d_out, int out_size) {
    const float* x  = (const float*)d_in[0];   // [1,2048,2048]
    const float* gw = (const float*)d_in[1];   // [32,2048]
    const float* Wg = (const float*)d_in[2];   // [32,2048,768]
    const float* Wu = (const float*)d_in[3];   // [32,2048,768]
    const float* Wd = (const float*)d_in[4];   // [32,768,2048]
    float* out = (float*)d_out;                // [1,2048,2048] fp32

    cudaMemsetAsync(out, 0, (size_t)T_TOK * HD * sizeof(float));
    zero_cnt_kernel<<<1, 32>>>();
    router_kernel<<<T_TOK, 256>>>(x, gw);
    scan_kernel<<<1, 32>>>();
    fill_kernel<<<(NPAIR + 255) / 256, 256>>>();

    dim3 ga(ID / 64, T_TOK / 64, NE);
    stageA_kernel<<<ga, 256>>>(x, Wg, Wu);
    dim3 gb(HD / 64, T_TOK / 64, NE);
    stageB_kernel<<<gb, 256>>>(Wd, out);
}

// round 5
// speedup vs baseline: 2.0601x; 2.0601x over previous
#include <cuda_runtime.h>
#include <cstdint>
#include <math.h>

#define T_TOK 2048
#define HD    2048
#define ID    768
#define NE    32
#define TOPK  4
#define NPAIR (T_TOK*TOPK)
#define MAXT  96
#define NPAD  (MAXT*128)

// ---------------- scratch ----------------
__device__ int   g_cnt[NE];
__device__ int   g_cur[NE];
__device__ int   g_tk_id[NPAIR];
__device__ float g_tk_w[NPAIR];
__device__ int   g_slot[NPAIR];
__device__ int   g_pair_tok[NPAD];
__device__ float g_pair_w[NPAD];
__device__ int   g_tile_e[MAXT];
__device__ int   g_tile_base[MAXT];
__device__ int   g_ntile;
__device__ float g_act[(size_t)NPAD * ID];
__device__ float g_pairout[(size_t)NPAD * HD];

// ---------------- helpers ----------------
__device__ __forceinline__ uint32_t smem_u32(const void* p) {
    uint32_t a;
    asm("{ .reg .u64 t; cvta.to.shared.u64 t, %1; cvt.u32.u64 %0, t; }" : "=r"(a) : "l"(p));
    return a;
}
__device__ __forceinline__ uint32_t tf32r(float f) {
    uint32_t u; asm("cvt.rna.tf32.f32 %0, %1;" : "=r"(u) : "f"(f)); return u;
}
__device__ __forceinline__ void cpasync16(uint32_t dst, const void* src) {
    asm volatile("cp.async.cg.shared.global [%0], [%1], 16;" :: "r"(dst), "l"(src));
}
#define CP_COMMIT() asm volatile("cp.async.commit_group;" ::: "memory")
#define CP_WAIT1()  asm volatile("cp.async.wait_group 1;" ::: "memory")
#define CP_WAIT0()  asm volatile("cp.async.wait_group 0;" ::: "memory")

__device__ __forceinline__ void mma8(float* c, const uint32_t* a, const uint32_t* b) {
    asm volatile("mma.sync.aligned.m16n8k8.row.col.f32.tf32.tf32.f32 "
        "{%0,%1,%2,%3}, {%4,%5,%6,%7}, {%8,%9}, {%0,%1,%2,%3};"
        : "+f"(c[0]), "+f"(c[1]), "+f"(c[2]), "+f"(c[3])
        : "r"(a[0]), "r"(a[1]), "r"(a[2]), "r"(a[3]), "r"(b[0]), "r"(b[1]));
}

#define KSTR 136                      // smem row stride (f32) -> conflict-free frags
#define SM_BYTES ((17408 + 256) * 4)  // 2xA(32x136) + 2xB(32x136) + toks + wts

// ---------------- small kernels ----------------
__global__ void zero_cnt_kernel() { if (threadIdx.x < NE) g_cnt[threadIdx.x] = 0; }

__global__ void router_kernel(const float* __restrict__ x, const float* __restrict__ gw) {
    __shared__ float xs[HD];
    __shared__ float lg[NE];
    int t = blockIdx.x;
    const float4* xv  = (const float4*)(x + (size_t)t * HD);
    float4*       xsv = (float4*)xs;
    for (int i = threadIdx.x; i < HD/4; i += blockDim.x) xsv[i] = xv[i];
    __syncthreads();
    int warp = threadIdx.x >> 5, lane = threadIdx.x & 31;
    for (int e = warp; e < NE; e += 8) {
        const float4* w = (const float4*)(gw + (size_t)e * HD);
        float s = 0.f;
        #pragma unroll 4
        for (int h = lane; h < HD/4; h += 32) {
            float4 wv = w[h]; float4 xr = xsv[h];
            s += wv.x*xr.x + wv.y*xr.y + wv.z*xr.z + wv.w*xr.w;
        }
        #pragma unroll
        for (int o = 16; o; o >>= 1) s += __shfl_xor_sync(0xffffffffu, s, o);
        if (lane == 0) lg[e] = s;
    }
    __syncthreads();
    if (threadIdx.x == 0) {
        int sel[TOPK]; float sv[TOPK];
        unsigned used = 0u;
        #pragma unroll
        for (int k = 0; k < TOPK; k++) {
            float best = -1e30f; int bi = 0;
            for (int e2 = 0; e2 < NE; e2++)
                if (!((used >> e2) & 1u) && lg[e2] > best) { best = lg[e2]; bi = e2; }
            used |= 1u << bi; sel[k] = bi; sv[k] = best;
        }
        float mx = sv[0], den = 0.f, ww[TOPK];
        #pragma unroll
        for (int k = 0; k < TOPK; k++) { ww[k] = expf(sv[k] - mx); den += ww[k]; }
        #pragma unroll
        for (int k = 0; k < TOPK; k++) {
            g_tk_id[t*TOPK + k] = sel[k];
            g_tk_w [t*TOPK + k] = ww[k] / den;
            atomicAdd(&g_cnt[sel[k]], 1);
        }
    }
}

__global__ void scanpad_kernel() {
    if (threadIdx.x != 0) return;
    int acc = 0, nt = 0;
    for (int e = 0; e < NE; e++) {
        int c = g_cnt[e];
        int tiles = (c + 127) >> 7;
        g_cur[e] = acc;
        for (int i = 0; i < tiles; i++) { g_tile_e[nt] = e; g_tile_base[nt] = acc + i*128; nt++; }
        acc += tiles * 128;
    }
    g_ntile = nt;
}

__global__ void zeropair_kernel() {
    int p = blockIdx.x * 256 + threadIdx.x;
    if (p < NPAD) { g_pair_tok[p] = 0; g_pair_w[p] = 0.f; }
}

__global__ void fill_kernel() {
    int p = blockIdx.x * 256 + threadIdx.x;
    if (p >= NPAIR) return;
    int e = g_tk_id[p];
    int pos = atomicAdd(&g_cur[e], 1);
    g_pair_tok[pos] = p >> 2;
    g_pair_w [pos] = g_tk_w[p];
    g_slot[p] = pos;
}

__global__ void combine_kernel(float* __restrict__ out) {
    int t = blockIdx.x;
    int s0 = g_slot[t*4+0], s1 = g_slot[t*4+1], s2 = g_slot[t*4+2], s3 = g_slot[t*4+3];
    const float4* p0 = (const float4*)(g_pairout + (size_t)s0 * HD);
    const float4* p1 = (const float4*)(g_pairout + (size_t)s1 * HD);
    const float4* p2 = (const float4*)(g_pairout + (size_t)s2 * HD);
    const float4* p3 = (const float4*)(g_pairout + (size_t)s3 * HD);
    float4* o = (float4*)(out + (size_t)t * HD);
    for (int i = threadIdx.x; i < HD/4; i += 256) {
        float4 a = p0[i], b = p1[i], c = p2[i], d = p3[i];
        o[i] = make_float4(a.x+b.x+c.x+d.x, a.y+b.y+c.y+d.y,
                           a.z+b.z+c.z+d.z, a.w+b.w+c.w+d.w);
    }
}

// ---------------- stage A: mma.sync tf32  silu(X Wg) * (X Wu) * w -> g_act ----------------
// block 128 thr, tile M=128 x Nphys=128 (64 Wg cols | 64 Wu cols), K-chunk 32, NC=64
__global__ void __launch_bounds__(128, 2)
stageA_kernel(const float* __restrict__ x,
              const float* __restrict__ Wg, const float* __restrict__ Wu) {
    int mt = blockIdx.x;
    if (mt >= g_ntile) return;
    int e = g_tile_e[mt], base = g_tile_base[mt];
    int nb = blockIdx.y;  // 64 I-cols per block

    extern __shared__ float sm[];
    float* sA[2] = { sm,        sm + 4352 };
    float* sB[2] = { sm + 8704, sm + 13056 };
    int*   toks  = (int*)(sm + 17408);
    float* wts   = sm + 17536;
    uint32_t sBu[2] = { smem_u32(sB[0]), smem_u32(sB[1]) };

    int t = threadIdx.x;
    toks[t] = g_pair_tok[base + t];
    wts[t]  = g_pair_w [base + t];
    __syncthreads();

    const float* xrow = x + (size_t)toks[t] * HD;        // this thread produces A row m=t
    const float* Wge = Wg + (size_t)e * HD * ID + (size_t)nb * 64;
    const float* Wue = Wu + (size_t)e * HD * ID + (size_t)nb * 64;
    int bc  = t & 31;                                    // 16B chunk within B row
    int bk0 = t >> 5;                                    // 0..3
    const float* bsrc = (bc < 16) ? (Wge + bc*4) : (Wue + (bc-16)*4);
    int bdst = (bc * 4) * 4;                             // byte offset within B row

    int lane = t & 31, wid = t >> 5;
    int wm = (wid >> 1) * 64;       // warp m base
    int wn = (wid & 1) * 32;        // warp n base within each half
    int grp = lane >> 2, tg = lane & 3;

    float acc[4][8][4];
    #pragma unroll
    for (int m = 0; m < 4; m++)
        #pragma unroll
        for (int n = 0; n < 8; n++)
            #pragma unroll
            for (int i = 0; i < 4; i++) acc[m][n][i] = 0.f;

    // preload chunk 0
    float4 rA[8];
    #pragma unroll
    for (int i = 0; i < 8; i++) rA[i] = *(const float4*)(xrow + i*4);
    #pragma unroll
    for (int i = 0; i < 8; i++) {
        int k = bk0 + 4*i;
        cpasync16(sBu[0] + k*(KSTR*4) + bdst, bsrc + (size_t)k * ID);
    }
    CP_COMMIT();

    for (int kc = 0; kc < 64; kc++) {
        int b = kc & 1;
        if (kc) __syncthreads();
        // STS A (cvt to tf32)
        #pragma unroll
        for (int i = 0; i < 8; i++) {
            float4 v = rA[i];
            sA[b][(4*i+0)*KSTR + t] = __uint_as_float(tf32r(v.x));
            sA[b][(4*i+1)*KSTR + t] = __uint_as_float(tf32r(v.y));
            sA[b][(4*i+2)*KSTR + t] = __uint_as_float(tf32r(v.z));
            sA[b][(4*i+3)*KSTR + t] = __uint_as_float(tf32r(v.w));
        }
        if (kc + 1 < 64) {
            const float* bs = bsrc + (size_t)(kc+1) * 32 * ID;
            #pragma unroll
            for (int i = 0; i < 8; i++) {
                int k = bk0 + 4*i;
                cpasync16(sBu[b^1] + k*(KSTR*4) + bdst, bs + (size_t)k * ID);
            }
            CP_COMMIT();
            const float* xs = xrow + (kc+1) * 32;
            #pragma unroll
            for (int i = 0; i < 8; i++) rA[i] = *(const float4*)(xs + i*4);
            CP_WAIT1();
        } else {
            CP_WAIT0();
        }
        __syncthreads();

        const float* A = sA[b];
        const float* B = sB[b];
        #pragma unroll
        for (int ks = 0; ks < 4; ks++) {
            int k = ks*8 + tg;
            uint32_t af[4][4];
            #pragma unroll
            for (int m = 0; m < 4; m++) {
                int mm = wm + m*16 + grp;
                af[m][0] = __float_as_uint(A[k*KSTR + mm]);
                af[m][1] = __float_as_uint(A[k*KSTR + mm + 8]);
                af[m][2] = __float_as_uint(A[(k+4)*KSTR + mm]);
                af[m][3] = __float_as_uint(A[(k+4)*KSTR + mm + 8]);
            }
            uint32_t bf[8][2];
            #pragma unroll
            for (int n = 0; n < 8; n++) {
                int col = (n < 4) ? (wn + n*8 + grp) : (64 + wn + (n-4)*8 + grp);
                bf[n][0] = tf32r(B[k*KSTR + col]);
                bf[n][1] = tf32r(B[(k+4)*KSTR + col]);
            }
            #pragma unroll
            for (int m = 0; m < 4; m++)
                #pragma unroll
                for (int n = 0; n < 8; n++)
                    mma8(acc[m][n], af[m], bf[n]);
        }
    }

    // epilogue: pair g (acc[m][n]) with u (acc[m][n+4]); silu(g)*u*wt; 8B stores
    #pragma unroll
    for (int m = 0; m < 4; m++) {
        int r0 = wm + m*16 + grp, r1 = r0 + 8;
        float w0 = wts[r0], w1 = wts[r1];
        #pragma unroll
        for (int n = 0; n < 4; n++) {
            int icol = wn + n*8 + 2*tg;
            float g0 = acc[m][n][0], g1 = acc[m][n][1];
            float g2 = acc[m][n][2], g3 = acc[m][n][3];
            float u0 = acc[m][n+4][0], u1 = acc[m][n+4][1];
            float u2 = acc[m][n+4][2], u3 = acc[m][n+4][3];
            float2 o0 = make_float2(g0 / (1.f + __expf(-g0)) * u0 * w0,
                                    g1 / (1.f + __expf(-g1)) * u1 * w0);
            float2 o1 = make_float2(g2 / (1.f + __expf(-g2)) * u2 * w1,
                                    g3 / (1.f + __expf(-g3)) * u3 * w1);
            *(float2*)(g_act + (size_t)(base + r0) * ID + nb*64 + icol) = o0;
            *(float2*)(g_act + (size_t)(base + r1) * ID + nb*64 + icol) = o1;
        }
    }
}

// ---------------- stage B: mma.sync tf32  g_act @ Wd -> g_pairout ----------------
// block 128 thr, tile M=128 x N=128, K-chunk 32, NC=24
__global__ void __launch_bounds__(128, 2)
stageB_kernel(const float* __restrict__ Wd) {
    int mt = blockIdx.x;
    if (mt >= g_ntile) return;
    int e = g_tile_e[mt], base = g_tile_base[mt];
    int nb = blockIdx.y;  // 128 HD-cols per block

    extern __shared__ float sm[];
    float* sA[2] = { sm,        sm + 4352 };
    float* sB[2] = { sm + 8704, sm + 13056 };
    uint32_t sBu[2] = { smem_u32(sB[0]), smem_u32(sB[1]) };

    int t = threadIdx.x;
    const float* arow = g_act + (size_t)(base + t) * ID;
    const float* We = Wd + (size_t)e * ID * HD + (size_t)nb * 128;
    int bc  = t & 31;
    int bk0 = t >> 5;
    const float* bsrc = We + bc*4;
    int bdst = (bc * 4) * 4;

    int lane = t & 31, wid = t >> 5;
    int wm = (wid >> 1) * 64;
    int wn = (wid & 1) * 64;
    int grp = lane >> 2, tg = lane & 3;

    float acc[4][8][4];
    #pragma unroll
    for (int m = 0; m < 4; m++)
        #pragma unroll
        for (int n = 0; n < 8; n++)
            #pragma unroll
            for (int i = 0; i < 4; i++) acc[m][n][i] = 0.f;

    float4 rA[8];
    #pragma unroll
    for (int i = 0; i < 8; i++) rA[i] = *(const float4*)(arow + i*4);
    #pragma unroll
    for (int i = 0; i < 8; i++) {
        int k = bk0 + 4*i;
        cpasync16(sBu[0] + k*(KSTR*4) + bdst, bsrc + (size_t)k * HD);
    }
    CP_COMMIT();

    for (int kc = 0; kc < 24; kc++) {
        int b = kc & 1;
        if (kc) __syncthreads();
        #pragma unroll
        for (int i = 0; i < 8; i++) {
            float4 v = rA[i];
            sA[b][(4*i+0)*KSTR + t] = __uint_as_float(tf32r(v.x));
            sA[b][(4*i+1)*KSTR + t] = __uint_as_float(tf32r(v.y));
            sA[b][(4*i+2)*KSTR + t] = __uint_as_float(tf32r(v.z));
            sA[b][(4*i+3)*KSTR + t] = __uint_as_float(tf32r(v.w));
        }
        if (kc + 1 < 24) {
            const float* bs = bsrc + (size_t)(kc+1) * 32 * HD;
            #pragma unroll
            for (int i = 0; i < 8; i++) {
                int k = bk0 + 4*i;
                cpasync16(sBu[b^1] + k*(KSTR*4) + bdst, bs + (size_t)k * HD);
            }
            CP_COMMIT();
            const float* as = arow + (kc+1) * 32;
            #pragma unroll
            for (int i = 0; i < 8; i++) rA[i] = *(const float4*)(as + i*4);
            CP_WAIT1();
        } else {
            CP_WAIT0();
        }
        __syncthreads();

        const float* A = sA[b];
        const float* B = sB[b];
        #pragma unroll
        for (int ks = 0; ks < 4; ks++) {
            int k = ks*8 + tg;
            uint32_t af[4][4];
            #pragma unroll
            for (int m = 0; m < 4; m++) {
                int mm = wm + m*16 + grp;
                af[m][0] = __float_as_uint(A[k*KSTR + mm]);
                af[m][1] = __float_as_uint(A[k*KSTR + mm + 8]);
                af[m][2] = __float_as_uint(A[(k+4)*KSTR + mm]);
                af[m][3] = __float_as_uint(A[(k+4)*KSTR + mm + 8]);
            }
            uint32_t bf[8][2];
            #pragma unroll
            for (int n = 0; n < 8; n++) {
                int col = wn + n*8 + grp;
                bf[n][0] = tf32r(B[k*KSTR + col]);
                bf[n][1] = tf32r(B[(k+4)*KSTR + col]);
            }
            #pragma unroll
            for (int m = 0; m < 4; m++)
                #pragma unroll
                for (int n = 0; n < 8; n++)
                    mma8(acc[m][n], af[m], bf[n]);
        }
    }

    #pragma unroll
    for (int m = 0; m < 4; m++) {
        int r0 = wm + m*16 + grp, r1 = r0 + 8;
        #pragma unroll
        for (int n = 0; n < 8; n++) {
            int col = wn + n*8 + 2*tg;
            *(float2*)(g_pairout + (size_t)(base + r0) * HD + nb*128 + col) =
                make_float2(acc[m][n][0], acc[m][n][1]);
            *(float2*)(g_pairout + (size_t)(base + r1) * HD + nb*128 + col) =
                make_float2(acc[m][n][2], acc[m][n][3]);
        }
    }
}

// ---------------- launch ----------------
extern "C" void kernel_launch(void* const* d_in, const int* in_sizes, int n_in,
                              void* d_out, int out_size) {
    const float* x  = (const float*)d_in[0];
    const float* gw = (const float*)d_in[1];
    const float* Wg = (const float*)d_in[2];
    const float* Wu = (const float*)d_in[3];
    const float* Wd = (const float*)d_in[4];
    float* out = (float*)d_out;

    cudaFuncSetAttribute(stageA_kernel, cudaFuncAttributeMaxDynamicSharedMemorySize, SM_BYTES);
    cudaFuncSetAttribute(stageB_kernel, cudaFuncAttributeMaxDynamicSharedMemorySize, SM_BYTES);

    zero_cnt_kernel<<<1, 32>>>();
    router_kernel<<<T_TOK, 256>>>(x, gw);
    scanpad_kernel<<<1, 1>>>();
    zeropair_kernel<<<NPAD/256, 256>>>();
    fill_kernel<<<NPAIR/256, 256>>>();
    stageA_kernel<<<dim3(MAXT, ID/64), 128, SM_BYTES>>>(x, Wg, Wu);
    stageB_kernel<<<dim3(MAXT, HD/128), 128, SM_BYTES>>>(Wd);
    combine_kernel<<<T_TOK, 256>>>(out);
}

// round 6
// speedup vs baseline: 2.1109x; 1.0247x over previous
#include <cuda_runtime.h>
#include <cstdint>
#include <math.h>

#define T_TOK 2048
#define HD    2048
#define ID    768
#define NE    32
#define TOPK  4
#define NPAIR (T_TOK*TOPK)
#define MAXT  96
#define NPAD  (MAXT*128)

// ---------------- scratch ----------------
__device__ int   g_cnt[NE];
__device__ int   g_cur[NE];
__device__ int   g_tk_id[NPAIR];
__device__ float g_tk_w[NPAIR];
__device__ int   g_slot[NPAIR];
__device__ int   g_pair_tok[NPAD];
__device__ float g_pair_w[NPAD];
__device__ int   g_tile_e[MAXT];
__device__ int   g_tile_base[MAXT];
__device__ int   g_ntile;
__device__ float g_xtf[(size_t)T_TOK * HD];          // X pre-rounded to tf32
__device__ float g_act[(size_t)NPAD * ID];           // stage-A out, tf32-rounded
__device__ float g_pairout[(size_t)NPAD * HD];

// ---------------- helpers ----------------
__device__ __forceinline__ uint32_t smem_u32(const void* p) {
    uint32_t a;
    asm("{ .reg .u64 t; cvta.to.shared.u64 t, %1; cvt.u32.u64 %0, t; }" : "=r"(a) : "l"(p));
    return a;
}
__device__ __forceinline__ uint32_t tf32r(float f) {
    uint32_t u; asm("cvt.rna.tf32.f32 %0, %1;" : "=r"(u) : "f"(f)); return u;
}
__device__ __forceinline__ void cpasync16(uint32_t dst, const void* src) {
    asm volatile("cp.async.cg.shared.global [%0], [%1], 16;" :: "r"(dst), "l"(src));
}
#define CP_COMMIT() asm volatile("cp.async.commit_group;" ::: "memory")
#define CP_WAIT1()  asm volatile("cp.async.wait_group 1;" ::: "memory")
#define CP_WAIT0()  asm volatile("cp.async.wait_group 0;" ::: "memory")

__device__ __forceinline__ void mma8(float* c, const uint32_t* a, const uint32_t* b) {
    asm volatile("mma.sync.aligned.m16n8k8.row.col.f32.tf32.tf32.f32 "
        "{%0,%1,%2,%3}, {%4,%5,%6,%7}, {%8,%9}, {%0,%1,%2,%3};"
        : "+f"(c[0]), "+f"(c[1]), "+f"(c[2]), "+f"(c[3])
        : "r"(a[0]), "r"(a[1]), "r"(a[2]), "r"(a[3]), "r"(b[0]), "r"(b[1]));
}

#define ASTR 40     // A smem row stride (floats): row-major [128][40]
#define BSTR 136    // B smem row stride (floats): k-major [32][136]
// floats: sA0 0, sA1 5120, sB0 10240, sB1 14592, wts 18944, end 19072
#define OFF_SA1 5120
#define OFF_SB0 10240
#define OFF_SB1 14592
#define OFF_WTS 18944
#define SM_BYTES (19072 * 4)

// ---------------- small kernels ----------------
__global__ void zero_cnt_kernel() { if (threadIdx.x < NE) g_cnt[threadIdx.x] = 0; }

__global__ void cvtx_kernel(const float* __restrict__ x) {
    int i = blockIdx.x * 256 + threadIdx.x;
    float4 v = ((const float4*)x)[i];
    float4 o = make_float4(__uint_as_float(tf32r(v.x)), __uint_as_float(tf32r(v.y)),
                           __uint_as_float(tf32r(v.z)), __uint_as_float(tf32r(v.w)));
    ((float4*)g_xtf)[i] = o;
}

__global__ void router_kernel(const float* __restrict__ x, const float* __restrict__ gw) {
    __shared__ float xs[HD];
    __shared__ float lg[NE];
    int t = blockIdx.x;
    const float4* xv  = (const float4*)(x + (size_t)t * HD);
    float4*       xsv = (float4*)xs;
    for (int i = threadIdx.x; i < HD/4; i += blockDim.x) xsv[i] = xv[i];
    __syncthreads();
    int warp = threadIdx.x >> 5, lane = threadIdx.x & 31;
    for (int e = warp; e < NE; e += 8) {
        const float4* w = (const float4*)(gw + (size_t)e * HD);
        float s = 0.f;
        #pragma unroll 4
        for (int h = lane; h < HD/4; h += 32) {
            float4 wv = w[h]; float4 xr = xsv[h];
            s += wv.x*xr.x + wv.y*xr.y + wv.z*xr.z + wv.w*xr.w;
        }
        #pragma unroll
        for (int o = 16; o; o >>= 1) s += __shfl_xor_sync(0xffffffffu, s, o);
        if (lane == 0) lg[e] = s;
    }
    __syncthreads();
    if (threadIdx.x == 0) {
        int sel[TOPK]; float sv[TOPK];
        unsigned used = 0u;
        #pragma unroll
        for (int k = 0; k < TOPK; k++) {
            float best = -1e30f; int bi = 0;
            for (int e2 = 0; e2 < NE; e2++)
                if (!((used >> e2) & 1u) && lg[e2] > best) { best = lg[e2]; bi = e2; }
            used |= 1u << bi; sel[k] = bi; sv[k] = best;
        }
        float mx = sv[0], den = 0.f, ww[TOPK];
        #pragma unroll
        for (int k = 0; k < TOPK; k++) { ww[k] = expf(sv[k] - mx); den += ww[k]; }
        #pragma unroll
        for (int k = 0; k < TOPK; k++) {
            g_tk_id[t*TOPK + k] = sel[k];
            g_tk_w [t*TOPK + k] = ww[k] / den;
            atomicAdd(&g_cnt[sel[k]], 1);
        }
    }
}

__global__ void scanpad_kernel() {
    if (threadIdx.x != 0) return;
    int acc = 0, nt = 0;
    for (int e = 0; e < NE; e++) {
        int c = g_cnt[e];
        int tiles = (c + 127) >> 7;
        g_cur[e] = acc;
        for (int i = 0; i < tiles; i++) { g_tile_e[nt] = e; g_tile_base[nt] = acc + i*128; nt++; }
        acc += tiles * 128;
    }
    g_ntile = nt;
}

__global__ void zeropair_kernel() {
    int p = blockIdx.x * 256 + threadIdx.x;
    if (p < NPAD) { g_pair_tok[p] = 0; g_pair_w[p] = 0.f; }
}

__global__ void fill_kernel() {
    int p = blockIdx.x * 256 + threadIdx.x;
    if (p >= NPAIR) return;
    int e = g_tk_id[p];
    int pos = atomicAdd(&g_cur[e], 1);
    g_pair_tok[pos] = p >> 2;
    g_pair_w [pos] = g_tk_w[p];
    g_slot[p] = pos;
}

__global__ void combine_kernel(float* __restrict__ out) {
    int t = blockIdx.x;
    int s0 = g_slot[t*4+0], s1 = g_slot[t*4+1], s2 = g_slot[t*4+2], s3 = g_slot[t*4+3];
    const float4* p0 = (const float4*)(g_pairout + (size_t)s0 * HD);
    const float4* p1 = (const float4*)(g_pairout + (size_t)s1 * HD);
    const float4* p2 = (const float4*)(g_pairout + (size_t)s2 * HD);
    const float4* p3 = (const float4*)(g_pairout + (size_t)s3 * HD);
    float4* o = (float4*)(out + (size_t)t * HD);
    for (int i = threadIdx.x; i < HD/4; i += 256) {
        float4 a = p0[i], b = p1[i], c = p2[i], d = p3[i];
        o[i] = make_float4(a.x+b.x+c.x+d.x, a.y+b.y+c.y+d.y,
                           a.z+b.z+c.z+d.z, a.w+b.w+c.w+d.w);
    }
}

// ---------------- stage A: mma.sync tf32, 256 thr, tile M128 x 64 logical I cols ----------------
__global__ void __launch_bounds__(256, 2)
stageA_kernel(const float* __restrict__ Wg, const float* __restrict__ Wu) {
    int mt = blockIdx.x;
    if (mt >= g_ntile) return;
    int e = g_tile_e[mt], base = g_tile_base[mt];
    int nb = blockIdx.y;  // 64 logical I cols

    extern __shared__ float sm[];
    float* sA[2] = { sm, sm + OFF_SA1 };
    float* sB[2] = { sm + OFF_SB0, sm + OFF_SB1 };
    float* wts = sm + OFF_WTS;
    uint32_t sAu[2] = { smem_u32(sA[0]), smem_u32(sA[1]) };
    uint32_t sBu[2] = { smem_u32(sB[0]), smem_u32(sB[1]) };

    int t = threadIdx.x;
    if (t < 128) wts[t] = g_pair_w[base + t];

    // A load mapping: thread -> (row, 64B segment)
    int arow = t >> 1, aseg = t & 1;
    const float* asrc0 = g_xtf + (size_t)g_pair_tok[base + arow] * HD + aseg * 16;
    uint32_t adst = 0u + (uint32_t)(arow * (ASTR*4)) + (uint32_t)(aseg * 64);
    // B load mapping: thread -> (k0, 16B col chunk)
    int bc = t & 31, bk0 = t >> 5;
    const float* Wge = Wg + (size_t)e * HD * ID + (size_t)nb * 64;
    const float* Wue = Wu + (size_t)e * HD * ID + (size_t)nb * 64;
    const float* bsrc0 = ((bc < 16) ? (Wge + bc*4) : (Wue + (bc-16)*4)) + (size_t)bk0 * ID;
    uint32_t bdst = (uint32_t)(bk0 * (BSTR*4) + bc * 16);

    int lane = t & 31, wid = t >> 5;
    int wm = (wid >> 1) * 32;        // 4 m-groups
    int wn = (wid & 1) * 32;         // 2 logical-n groups
    int grp = lane >> 2, tg = lane & 3;

    float accg[2][4][4], accu[2][4][4];
    #pragma unroll
    for (int m = 0; m < 2; m++)
        #pragma unroll
        for (int n = 0; n < 4; n++)
            #pragma unroll
            for (int i = 0; i < 4; i++) { accg[m][n][i] = 0.f; accu[m][n][i] = 0.f; }

    // prologue: chunk 0 into buffer 0
    #pragma unroll
    for (int i = 0; i < 4; i++) cpasync16(sAu[0] + adst + i*16, asrc0 + i*4);
    #pragma unroll
    for (int i = 0; i < 4; i++) cpasync16(sBu[0] + bdst + i*8*(BSTR*4), bsrc0 + (size_t)i*8*ID);
    CP_COMMIT();

    for (int kc = 0; kc < 64; kc++) {
        int b = kc & 1;
        __syncthreads();   // all warps done computing buffer b^1 (prev-prev chunk)
        if (kc + 1 < 64) {
            const float* as = asrc0 + (size_t)(kc+1) * 32;
            const float* bs = bsrc0 + (size_t)(kc+1) * 32 * ID;
            #pragma unroll
            for (int i = 0; i < 4; i++) cpasync16(sAu[b^1] + adst + i*16, as + i*4);
            #pragma unroll
            for (int i = 0; i < 4; i++) cpasync16(sBu[b^1] + bdst + i*8*(BSTR*4), bs + (size_t)i*8*ID);
            CP_COMMIT();
            CP_WAIT1();
        } else {
            CP_WAIT0();
        }
        __syncthreads();

        const float* A = sA[b];
        const float* B = sB[b];
        #pragma unroll
        for (int ks = 0; ks < 4; ks++) {
            int k = ks*8 + tg;
            uint32_t af[2][4];
            #pragma unroll
            for (int m = 0; m < 2; m++) {
                int mm = wm + m*16 + grp;
                af[m][0] = __float_as_uint(A[mm*ASTR + k]);
                af[m][1] = __float_as_uint(A[(mm+8)*ASTR + k]);
                af[m][2] = __float_as_uint(A[mm*ASTR + k + 4]);
                af[m][3] = __float_as_uint(A[(mm+8)*ASTR + k + 4]);
            }
            #pragma unroll
            for (int n = 0; n < 4; n++) {
                int colg = wn + n*8 + grp;
                uint32_t bf[2];
                bf[0] = tf32r(B[k*BSTR + colg]);
                bf[1] = tf32r(B[(k+4)*BSTR + colg]);
                mma8(accg[0][n], af[0], bf);
                mma8(accg[1][n], af[1], bf);
                bf[0] = tf32r(B[k*BSTR + 64 + colg]);
                bf[1] = tf32r(B[(k+4)*BSTR + 64 + colg]);
                mma8(accu[0][n], af[0], bf);
                mma8(accu[1][n], af[1], bf);
            }
        }
    }

    // epilogue: silu(g)*u*wt, round to tf32, store float2
    #pragma unroll
    for (int m = 0; m < 2; m++) {
        int r0 = wm + m*16 + grp, r1 = r0 + 8;
        float w0 = wts[r0], w1 = wts[r1];
        #pragma unroll
        for (int n = 0; n < 4; n++) {
            int icol = nb*64 + wn + n*8 + 2*tg;
            float g0 = accg[m][n][0], g1 = accg[m][n][1];
            float g2 = accg[m][n][2], g3 = accg[m][n][3];
            float u0 = accu[m][n][0], u1 = accu[m][n][1];
            float u2 = accu[m][n][2], u3 = accu[m][n][3];
            float v0 = g0 / (1.f + __expf(-g0)) * u0 * w0;
            float v1 = g1 / (1.f + __expf(-g1)) * u1 * w0;
            float v2 = g2 / (1.f + __expf(-g2)) * u2 * w1;
            float v3 = g3 / (1.f + __expf(-g3)) * u3 * w1;
            *(float2*)(g_act + (size_t)(base + r0) * ID + icol) =
                make_float2(__uint_as_float(tf32r(v0)), __uint_as_float(tf32r(v1)));
            *(float2*)(g_act + (size_t)(base + r1) * ID + icol) =
                make_float2(__uint_as_float(tf32r(v2)), __uint_as_float(tf32r(v3)));
        }
    }
}

// ---------------- stage B: mma.sync tf32, 256 thr, tile M128 x N128 ----------------
__global__ void __launch_bounds__(256, 2)
stageB_kernel(const float* __restrict__ Wd) {
    int mt = blockIdx.x;
    if (mt >= g_ntile) return;
    int e = g_tile_e[mt], base = g_tile_base[mt];
    int nb = blockIdx.y;  // 128 HD cols

    extern __shared__ float sm[];
    float* sA[2] = { sm, sm + OFF_SA1 };
    float* sB[2] = { sm + OFF_SB0, sm + OFF_SB1 };
    uint32_t sAu[2] = { smem_u32(sA[0]), smem_u32(sA[1]) };
    uint32_t sBu[2] = { smem_u32(sB[0]), smem_u32(sB[1]) };

    int t = threadIdx.x;
    int arow = t >> 1, aseg = t & 1;
    const float* asrc0 = g_act + (size_t)(base + arow) * ID + aseg * 16;
    uint32_t adst = (uint32_t)(arow * (ASTR*4) + aseg * 64);
    int bc = t & 31, bk0 = t >> 5;
    const float* We = Wd + (size_t)e * ID * HD + (size_t)nb * 128;
    const float* bsrc0 = We + bc*4 + (size_t)bk0 * HD;
    uint32_t bdst = (uint32_t)(bk0 * (BSTR*4) + bc * 16);

    int lane = t & 31, wid = t >> 5;
    int wm = (wid >> 1) * 32;
    int wn = (wid & 1) * 64;
    int grp = lane >> 2, tg = lane & 3;

    float acc[2][8][4];
    #pragma unroll
    for (int m = 0; m < 2; m++)
        #pragma unroll
        for (int n = 0; n < 8; n++)
            #pragma unroll
            for (int i = 0; i < 4; i++) acc[m][n][i] = 0.f;

    #pragma unroll
    for (int i = 0; i < 4; i++) cpasync16(sAu[0] + adst + i*16, asrc0 + i*4);
    #pragma unroll
    for (int i = 0; i < 4; i++) cpasync16(sBu[0] + bdst + i*8*(BSTR*4), bsrc0 + (size_t)i*8*HD);
    CP_COMMIT();

    for (int kc = 0; kc < 24; kc++) {
        int b = kc & 1;
        __syncthreads();
        if (kc + 1 < 24) {
            const float* as = asrc0 + (size_t)(kc+1) * 32;
            const float* bs = bsrc0 + (size_t)(kc+1) * 32 * HD;
            #pragma unroll
            for (int i = 0; i < 4; i++) cpasync16(sAu[b^1] + adst + i*16, as + i*4);
            #pragma unroll
            for (int i = 0; i < 4; i++) cpasync16(sBu[b^1] + bdst + i*8*(BSTR*4), bs + (size_t)i*8*HD);
            CP_COMMIT();
            CP_WAIT1();
        } else {
            CP_WAIT0();
        }
        __syncthreads();

        const float* A = sA[b];
        const float* B = sB[b];
        #pragma unroll
        for (int ks = 0; ks < 4; ks++) {
            int k = ks*8 + tg;
            uint32_t af[2][4];
            #pragma unroll
            for (int m = 0; m < 2; m++) {
                int mm = wm + m*16 + grp;
                af[m][0] = __float_as_uint(A[mm*ASTR + k]);
                af[m][1] = __float_as_uint(A[(mm+8)*ASTR + k]);
                af[m][2] = __float_as_uint(A[mm*ASTR + k + 4]);
                af[m][3] = __float_as_uint(A[(mm+8)*ASTR + k + 4]);
            }
            #pragma unroll
            for (int n = 0; n < 8; n++) {
                int col = wn + n*8 + grp;
                uint32_t bf[2];
                bf[0] = tf32r(B[k*BSTR + col]);
                bf[1] = tf32r(B[(k+4)*BSTR + col]);
                mma8(acc[0][n], af[0], bf);
                mma8(acc[1][n], af[1], bf);
            }
        }
    }

    #pragma unroll
    for (int m = 0; m < 2; m++) {
        int r0 = wm + m*16 + grp, r1 = r0 + 8;
        #pragma unroll
        for (int n = 0; n < 8; n++) {
            int col = nb*128 + wn + n*8 + 2*tg;
            *(float2*)(g_pairout + (size_t)(base + r0) * HD + col) =
                make_float2(acc[m][n][0], acc[m][n][1]);
            *(float2*)(g_pairout + (size_t)(base + r1) * HD + col) =
                make_float2(acc[m][n][2], acc[m][n][3]);
        }
    }
}

// ---------------- launch ----------------
extern "C" void kernel_launch(void* const* d_in, const int* in_sizes, int n_in,
                              void* d_out, int out_size) {
    const float* x  = (const float*)d_in[0];
    const float* gw = (const float*)d_in[1];
    const float* Wg = (const float*)d_in[2];
    const float* Wu = (const float*)d_in[3];
    const float* Wd = (const float*)d_in[4];
    float* out = (float*)d_out;

    cudaFuncSetAttribute(stageA_kernel, cudaFuncAttributeMaxDynamicSharedMemorySize, SM_BYTES);
    cudaFuncSetAttribute(stageB_kernel, cudaFuncAttributeMaxDynamicSharedMemorySize, SM_BYTES);

    zero_cnt_kernel<<<1, 32>>>();
    cvtx_kernel<<<(T_TOK*HD/4)/256, 256>>>(x);
    router_kernel<<<T_TOK, 256>>>(x, gw);
    scanpad_kernel<<<1, 1>>>();
    zeropair_kernel<<<NPAD/256, 256>>>();
    fill_kernel<<<NPAIR/256, 256>>>();
    stageA_kernel<<<dim3(MAXT, ID/64), 256, SM_BYTES>>>(Wg, Wu);
    stageB_kernel<<<dim3(MAXT, HD/128), 256, SM_BYTES>>>(Wd);
    combine_kernel<<<T_TOK, 256>>>(out);
}

// round 7
// speedup vs baseline: 2.4211x; 1.1469x over previous
#include <cuda_runtime.h>
#include <cstdint>
#include <math.h>

#define T_TOK 2048
#define HD    2048
#define ID    768
#define NE    32
#define TOPK  4
#define NPAIR (T_TOK*TOPK)
#define MAXT  96
#define NPAD  (MAXT*128)

// ---------------- scratch ----------------
__device__ int   g_cnt[NE];
__device__ int   g_cur[NE];
__device__ int   g_tk_id[NPAIR];
__device__ float g_tk_w[NPAIR];
__device__ int   g_slot[NPAIR];
__device__ int   g_pair_tok[NPAD];
__device__ float g_pair_w[NPAD];
__device__ int   g_tile_e[MAXT];
__device__ int   g_tile_base[MAXT];
__device__ int   g_ntile;
__device__ float g_xtf[(size_t)T_TOK * HD];          // X pre-rounded to tf32
__device__ float g_act[(size_t)NPAD * ID];           // stage-A out, tf32-rounded
__device__ float g_pairout[(size_t)NPAD * HD];

// ---------------- helpers ----------------
__device__ __forceinline__ uint32_t smem_u32(const void* p) {
    uint32_t a;
    asm("{ .reg .u64 t; cvta.to.shared.u64 t, %1; cvt.u32.u64 %0, t; }" : "=r"(a) : "l"(p));
    return a;
}
__device__ __forceinline__ uint32_t tf32r(float f) {
    uint32_t u; asm("cvt.rna.tf32.f32 %0, %1;" : "=r"(u) : "f"(f)); return u;
}
__device__ __forceinline__ void cpasync16(uint32_t dst, const void* src) {
    asm volatile("cp.async.cg.shared.global [%0], [%1], 16;" :: "r"(dst), "l"(src));
}
#define CP_COMMIT() asm volatile("cp.async.commit_group;" ::: "memory")
#define CP_WAIT1()  asm volatile("cp.async.wait_group 1;" ::: "memory")
#define CP_WAIT0()  asm volatile("cp.async.wait_group 0;" ::: "memory")

__device__ __forceinline__ void mma8(float* c, const uint32_t* a, const uint32_t* b) {
    asm volatile("mma.sync.aligned.m16n8k8.row.col.f32.tf32.tf32.f32 "
        "{%0,%1,%2,%3}, {%4,%5,%6,%7}, {%8,%9}, {%0,%1,%2,%3};"
        : "+f"(c[0]), "+f"(c[1]), "+f"(c[2]), "+f"(c[3])
        : "r"(a[0]), "r"(a[1]), "r"(a[2]), "r"(a[3]), "r"(b[0]), "r"(b[1]));
}
#define LDSM4(r0,r1,r2,r3,addr) \
    asm volatile("ldmatrix.sync.aligned.m8n8.x4.shared.b16 {%0,%1,%2,%3}, [%4];" \
        : "=r"(r0), "=r"(r1), "=r"(r2), "=r"(r3) : "r"(addr))

#define ASTR 36     // A smem row stride (floats): 144B = 9x16B -> LDSM conflict-free
#define BSTR 136    // B smem k-row stride (floats): scalar LDS conflict-free
// floats: sA0 0, sA1 4608, sB0 9216, sB1 13568, wts 17920, end 18048
#define OFF_SA1 4608
#define OFF_SB0 9216
#define OFF_SB1 13568
#define OFF_WTS 17920
#define SM_BYTES (18048 * 4)

// ---------------- small kernels ----------------
__global__ void zero_cnt_kernel() { if (threadIdx.x < NE) g_cnt[threadIdx.x] = 0; }

__global__ void cvtx_kernel(const float* __restrict__ x) {
    int i = blockIdx.x * 256 + threadIdx.x;
    float4 v = ((const float4*)x)[i];
    float4 o = make_float4(__uint_as_float(tf32r(v.x)), __uint_as_float(tf32r(v.y)),
                           __uint_as_float(tf32r(v.z)), __uint_as_float(tf32r(v.w)));
    ((float4*)g_xtf)[i] = o;
}

__global__ void router_kernel(const float* __restrict__ x, const float* __restrict__ gw) {
    __shared__ float xs[HD];
    __shared__ float lg[NE];
    int t = blockIdx.x;
    const float4* xv  = (const float4*)(x + (size_t)t * HD);
    float4*       xsv = (float4*)xs;
    for (int i = threadIdx.x; i < HD/4; i += blockDim.x) xsv[i] = xv[i];
    __syncthreads();
    int warp = threadIdx.x >> 5, lane = threadIdx.x & 31;
    for (int e = warp; e < NE; e += 8) {
        const float4* w = (const float4*)(gw + (size_t)e * HD);
        float s = 0.f;
        #pragma unroll 4
        for (int h = lane; h < HD/4; h += 32) {
            float4 wv = w[h]; float4 xr = xsv[h];
            s += wv.x*xr.x + wv.y*xr.y + wv.z*xr.z + wv.w*xr.w;
        }
        #pragma unroll
        for (int o = 16; o; o >>= 1) s += __shfl_xor_sync(0xffffffffu, s, o);
        if (lane == 0) lg[e] = s;
    }
    __syncthreads();
    if (threadIdx.x == 0) {
        int sel[TOPK]; float sv[TOPK];
        unsigned used = 0u;
        #pragma unroll
        for (int k = 0; k < TOPK; k++) {
            float best = -1e30f; int bi = 0;
            for (int e2 = 0; e2 < NE; e2++)
                if (!((used >> e2) & 1u) && lg[e2] > best) { best = lg[e2]; bi = e2; }
            used |= 1u << bi; sel[k] = bi; sv[k] = best;
        }
        float mx = sv[0], den = 0.f, ww[TOPK];
        #pragma unroll
        for (int k = 0; k < TOPK; k++) { ww[k] = expf(sv[k] - mx); den += ww[k]; }
        #pragma unroll
        for (int k = 0; k < TOPK; k++) {
            g_tk_id[t*TOPK + k] = sel[k];
            g_tk_w [t*TOPK + k] = ww[k] / den;
            atomicAdd(&g_cnt[sel[k]], 1);
        }
    }
}

__global__ void scanpad_kernel() {
    if (threadIdx.x != 0) return;
    int acc = 0, nt = 0;
    for (int e = 0; e < NE; e++) {
        int c = g_cnt[e];
        int tiles = (c + 127) >> 7;
        g_cur[e] = acc;
        for (int i = 0; i < tiles; i++) { g_tile_e[nt] = e; g_tile_base[nt] = acc + i*128; nt++; }
        acc += tiles * 128;
    }
    g_ntile = nt;
}

__global__ void zeropair_kernel() {
    int p = blockIdx.x * 256 + threadIdx.x;
    if (p < NPAD) { g_pair_tok[p] = 0; g_pair_w[p] = 0.f; }
}

__global__ void fill_kernel() {
    int p = blockIdx.x * 256 + threadIdx.x;
    if (p >= NPAIR) return;
    int e = g_tk_id[p];
    int pos = atomicAdd(&g_cur[e], 1);
    g_pair_tok[pos] = p >> 2;
    g_pair_w [pos] = g_tk_w[p];
    g_slot[p] = pos;
}

__global__ void combine_kernel(float* __restrict__ out) {
    int t = blockIdx.x;
    int s0 = g_slot[t*4+0], s1 = g_slot[t*4+1], s2 = g_slot[t*4+2], s3 = g_slot[t*4+3];
    const float4* p0 = (const float4*)(g_pairout + (size_t)s0 * HD);
    const float4* p1 = (const float4*)(g_pairout + (size_t)s1 * HD);
    const float4* p2 = (const float4*)(g_pairout + (size_t)s2 * HD);
    const float4* p3 = (const float4*)(g_pairout + (size_t)s3 * HD);
    float4* o = (float4*)(out + (size_t)t * HD);
    for (int i = threadIdx.x; i < HD/4; i += 256) {
        float4 a = p0[i], b = p1[i], c = p2[i], d = p3[i];
        o[i] = make_float4(a.x+b.x+c.x+d.x, a.y+b.y+c.y+d.y,
                           a.z+b.z+c.z+d.z, a.w+b.w+c.w+d.w);
    }
}

// ---------------- stage A: warp tile m64 x n16-logical, ldmatrix A frags ----------------
__global__ void __launch_bounds__(256, 2)
stageA_kernel(const float* __restrict__ Wg, const float* __restrict__ Wu) {
    int mt = blockIdx.y;
    if (mt >= g_ntile) return;
    int e = g_tile_e[mt], base = g_tile_base[mt];
    int nb = blockIdx.x;  // 64 logical I cols

    extern __shared__ float sm[];
    float* sB[2] = { sm + OFF_SB0, sm + OFF_SB1 };
    float* wts = sm + OFF_WTS;
    uint32_t sAu[2] = { smem_u32(sm), smem_u32(sm + OFF_SA1) };
    uint32_t sBu[2] = { smem_u32(sB[0]), smem_u32(sB[1]) };

    int t = threadIdx.x;
    if (t < 128) wts[t] = g_pair_w[base + t];

    // A producer: thread -> (row, 64B half)
    int arow = t >> 1, aseg = t & 1;
    const float* asrc0 = g_xtf + (size_t)g_pair_tok[base + arow] * HD + aseg * 16;
    uint32_t adst = (uint32_t)(arow * (ASTR*4) + aseg * 64);
    // B producer: thread -> (k0, 16B col chunk)
    int bc = t & 31, bk0 = t >> 5;
    const float* Wge = Wg + (size_t)e * HD * ID + (size_t)nb * 64;
    const float* Wue = Wu + (size_t)e * HD * ID + (size_t)nb * 64;
    const float* bsrc0 = ((bc < 16) ? (Wge + bc*4) : (Wue + (bc-16)*4)) + (size_t)bk0 * ID;
    uint32_t bdst = (uint32_t)(bk0 * (BSTR*4) + bc * 16);

    int lane = t & 31, wid = t >> 5;
    int wm  = (wid & 1) * 64;        // 2 m-warp groups
    int wng = (wid >> 1) * 16;       // 4 logical-n warp groups
    int grp = lane >> 2, tg = lane & 3;
    uint32_t aoff = (uint32_t)((wm + (lane & 15)) * (ASTR*4) + (lane >> 4) * 16);

    float acc[4][4][4];   // [mfrag][0,1=g 2,3=u][frag]
    #pragma unroll
    for (int m = 0; m < 4; m++)
        #pragma unroll
        for (int n = 0; n < 4; n++)
            #pragma unroll
            for (int i = 0; i < 4; i++) acc[m][n][i] = 0.f;

    #pragma unroll
    for (int i = 0; i < 4; i++) cpasync16(sAu[0] + adst + i*16, asrc0 + i*4);
    #pragma unroll
    for (int i = 0; i < 4; i++) cpasync16(sBu[0] + bdst + i*8*(BSTR*4), bsrc0 + (size_t)i*8*ID);
    CP_COMMIT();

    for (int kc = 0; kc < 64; kc++) {
        int b = kc & 1;
        __syncthreads();
        if (kc + 1 < 64) {
            const float* as = asrc0 + (size_t)(kc+1) * 32;
            const float* bs = bsrc0 + (size_t)(kc+1) * 32 * ID;
            #pragma unroll
            for (int i = 0; i < 4; i++) cpasync16(sAu[b^1] + adst + i*16, as + i*4);
            #pragma unroll
            for (int i = 0; i < 4; i++) cpasync16(sBu[b^1] + bdst + i*8*(BSTR*4), bs + (size_t)i*8*ID);
            CP_COMMIT();
            CP_WAIT1();
        } else {
            CP_WAIT0();
        }
        __syncthreads();

        uint32_t abase = sAu[b] + aoff;
        const float* B = sB[b];
        #pragma unroll
        for (int ks = 0; ks < 4; ks++) {
            uint32_t af[4][4];
            #pragma unroll
            for (int m = 0; m < 4; m++)
                LDSM4(af[m][0], af[m][1], af[m][2], af[m][3], abase + m*(16*ASTR*4) + ks*32);
            int k = ks*8 + tg;
            #pragma unroll
            for (int n = 0; n < 2; n++) {
                int colg = wng + n*8 + grp;
                uint32_t bf[2];
                bf[0] = tf32r(B[k*BSTR + colg]);
                bf[1] = tf32r(B[(k+4)*BSTR + colg]);
                #pragma unroll
                for (int m = 0; m < 4; m++) mma8(acc[m][n], af[m], bf);
                bf[0] = tf32r(B[k*BSTR + 64 + colg]);
                bf[1] = tf32r(B[(k+4)*BSTR + 64 + colg]);
                #pragma unroll
                for (int m = 0; m < 4; m++) mma8(acc[m][n+2], af[m], bf);
            }
        }
    }

    // epilogue: silu(g)*u*wt, round to tf32, float2 stores
    #pragma unroll
    for (int m = 0; m < 4; m++) {
        int r0 = wm + m*16 + grp, r1 = r0 + 8;
        float w0 = wts[r0], w1 = wts[r1];
        #pragma unroll
        for (int n = 0; n < 2; n++) {
            int icol = nb*64 + wng + n*8 + 2*tg;
            float g0 = acc[m][n][0], g1 = acc[m][n][1];
            float g2 = acc[m][n][2], g3 = acc[m][n][3];
            float u0 = acc[m][n+2][0], u1 = acc[m][n+2][1];
            float u2 = acc[m][n+2][2], u3 = acc[m][n+2][3];
            float v0 = g0 / (1.f + __expf(-g0)) * u0 * w0;
            float v1 = g1 / (1.f + __expf(-g1)) * u1 * w0;
            float v2 = g2 / (1.f + __expf(-g2)) * u2 * w1;
            float v3 = g3 / (1.f + __expf(-g3)) * u3 * w1;
            *(float2*)(g_act + (size_t)(base + r0) * ID + icol) =
                make_float2(__uint_as_float(tf32r(v0)), __uint_as_float(tf32r(v1)));
            *(float2*)(g_act + (size_t)(base + r1) * ID + icol) =
                make_float2(__uint_as_float(tf32r(v2)), __uint_as_float(tf32r(v3)));
        }
    }
}

// ---------------- stage B: warp tile m64 x n32, ldmatrix A frags ----------------
__global__ void __launch_bounds__(256, 2)
stageB_kernel(const float* __restrict__ Wd) {
    int mt = blockIdx.y;
    if (mt >= g_ntile) return;
    int e = g_tile_e[mt], base = g_tile_base[mt];
    int nb = blockIdx.x;  // 128 HD cols

    extern __shared__ float sm[];
    float* sB[2] = { sm + OFF_SB0, sm + OFF_SB1 };
    uint32_t sAu[2] = { smem_u32(sm), smem_u32(sm + OFF_SA1) };
    uint32_t sBu[2] = { smem_u32(sB[0]), smem_u32(sB[1]) };

    int t = threadIdx.x;
    int arow = t >> 1, aseg = t & 1;
    const float* asrc0 = g_act + (size_t)(base + arow) * ID + aseg * 16;
    uint32_t adst = (uint32_t)(arow * (ASTR*4) + aseg * 64);
    int bc = t & 31, bk0 = t >> 5;
    const float* We = Wd + (size_t)e * ID * HD + (size_t)nb * 128;
    const float* bsrc0 = We + bc*4 + (size_t)bk0 * HD;
    uint32_t bdst = (uint32_t)(bk0 * (BSTR*4) + bc * 16);

    int lane = t & 31, wid = t >> 5;
    int wm = (wid & 1) * 64;
    int wn = (wid >> 1) * 32;
    int grp = lane >> 2, tg = lane & 3;
    uint32_t aoff = (uint32_t)((wm + (lane & 15)) * (ASTR*4) + (lane >> 4) * 16);

    float acc[4][4][4];
    #pragma unroll
    for (int m = 0; m < 4; m++)
        #pragma unroll
        for (int n = 0; n < 4; n++)
            #pragma unroll
            for (int i = 0; i < 4; i++) acc[m][n][i] = 0.f;

    #pragma unroll
    for (int i = 0; i < 4; i++) cpasync16(sAu[0] + adst + i*16, asrc0 + i*4);
    #pragma unroll
    for (int i = 0; i < 4; i++) cpasync16(sBu[0] + bdst + i*8*(BSTR*4), bsrc0 + (size_t)i*8*HD);
    CP_COMMIT();

    for (int kc = 0; kc < 24; kc++) {
        int b = kc & 1;
        __syncthreads();
        if (kc + 1 < 24) {
            const float* as = asrc0 + (size_t)(kc+1) * 32;
            const float* bs = bsrc0 + (size_t)(kc+1) * 32 * HD;
            #pragma unroll
            for (int i = 0; i < 4; i++) cpasync16(sAu[b^1] + adst + i*16, as + i*4);
            #pragma unroll
            for (int i = 0; i < 4; i++) cpasync16(sBu[b^1] + bdst + i*8*(BSTR*4), bs + (size_t)i*8*HD);
            CP_COMMIT();
            CP_WAIT1();
        } else {
            CP_WAIT0();
        }
        __syncthreads();

        uint32_t abase = sAu[b] + aoff;
        const float* B = sB[b];
        #pragma unroll
        for (int ks = 0; ks < 4; ks++) {
            uint32_t af[4][4];
            #pragma unroll
            for (int m = 0; m < 4; m++)
                LDSM4(af[m][0], af[m][1], af[m][2], af[m][3], abase + m*(16*ASTR*4) + ks*32);
            int k = ks*8 + tg;
            #pragma unroll
            for (int n = 0; n < 4; n++) {
                int col = wn + n*8 + grp;
                uint32_t bf[2];
                bf[0] = tf32r(B[k*BSTR + col]);
                bf[1] = tf32r(B[(k+4)*BSTR + col]);
                #pragma unroll
                for (int m = 0; m < 4; m++) mma8(acc[m][n], af[m], bf);
            }
        }
    }

    #pragma unroll
    for (int m = 0; m < 4; m++) {
        int r0 = wm + m*16 + grp, r1 = r0 + 8;
        #pragma unroll
        for (int n = 0; n < 4; n++) {
            int col = nb*128 + wn + n*8 + 2*tg;
            *(float2*)(g_pairout + (size_t)(base + r0) * HD + col) =
                make_float2(acc[m][n][0], acc[m][n][1]);
            *(float2*)(g_pairout + (size_t)(base + r1) * HD + col) =
                make_float2(acc[m][n][2], acc[m][n][3]);
        }
    }
}

// ---------------- launch ----------------
extern "C" void kernel_launch(void* const* d_in, const int* in_sizes, int n_in,
                              void* d_out, int out_size) {
    const float* x  = (const float*)d_in[0];
    const float* gw = (const float*)d_in[1];
    const float* Wg = (const float*)d_in[2];
    const float* Wu = (const float*)d_in[3];
    const float* Wd = (const float*)d_in[4];
    float* out = (float*)d_out;

    cudaFuncSetAttribute(stageA_kernel, cudaFuncAttributeMaxDynamicSharedMemorySize, SM_BYTES);
    cudaFuncSetAttribute(stageB_kernel, cudaFuncAttributeMaxDynamicSharedMemorySize, SM_BYTES);

    zero_cnt_kernel<<<1, 32>>>();
    cvtx_kernel<<<(T_TOK*HD/4)/256, 256>>>(x);
    router_kernel<<<T_TOK, 256>>>(x, gw);
    scanpad_kernel<<<1, 1>>>();
    zeropair_kernel<<<NPAD/256, 256>>>();
    fill_kernel<<<NPAIR/256, 256>>>();
    stageA_kernel<<<dim3(ID/64, MAXT), 256, SM_BYTES>>>(Wg, Wu);
    stageB_kernel<<<dim3(HD/128, MAXT), 256, SM_BYTES>>>(Wd);
    combine_kernel<<<T_TOK, 256>>>(out);
}